// round 10
// baseline (speedup 1.0000x reference)
#include <cuda_runtime.h>
#include <math.h>

#define H 256

#define BM 64
#define BJ 64
#define KC 16

#define HMAX_ROWS 32768
#define LEAF_N    262144
#define N_TOTAL   299593

// Scratch (device globals -- no allocation allowed)
__device__ float g_enc[(size_t)N_TOTAL * H];          // encoder outputs per tree node
__device__ float g_el [(size_t)LEAF_N  * H];          // left-LSTM final hidden
__device__ float g_er [(size_t)LEAF_N  * H];          // right-LSTM final hidden
__device__ float g_h[2][2][(size_t)HMAX_ROWS * H];    // [side][ping] hidden state
__device__ float g_c[2][2][(size_t)HMAX_ROWS * H];    // [side][ping] cell state

__device__ __forceinline__ float sigm(float x) { return 1.0f / (1.0f + expf(-x)); }

// One LSTM step for both the left (z=0) and right (z=1) chains.
// gates[n,1024] = X[n,256] @ Wih^T (+ Hprev[n,256] @ Whh^T) + bih + bhh
// X rows come from node_init (xsrc=0) or g_enc (xsrc=1) at row = xoff + m*xstr.
__global__ __launch_bounds__(256)
void lstm_step_kernel(
    const float* __restrict__ node_init,
    const float* __restrict__ Wih_l, const float* __restrict__ Whh_l,
    const float* __restrict__ bih_l, const float* __restrict__ bhh_l,
    const float* __restrict__ Wih_r, const float* __restrict__ Whh_r,
    const float* __restrict__ bih_r, const float* __restrict__ bhh_r,
    int n, int first, int last, int pp,
    int xsrc_l, long long xoff_l, int xstr_l,
    int xsrc_r, long long xoff_r, int xstr_r)
{
    const int side = blockIdx.z;
    const float* Wih = side ? Wih_r : Wih_l;
    const float* Whh = side ? Whh_r : Whh_l;
    const float* bih = side ? bih_r : bih_l;
    const float* bhh = side ? bhh_r : bhh_l;
    const int       xsrc = side ? xsrc_r : xsrc_l;
    const long long xoff = side ? xoff_r : xoff_l;
    const int       xstr = side ? xstr_r : xstr_l;

    const float* xbase = xsrc ? g_enc : node_init;
    const float* h_in  = g_h[side][pp];
    const float* c_in  = g_c[side][pp];
    float* h_out = last ? (side ? g_er : g_el) : g_h[side][pp ^ 1];
    float* c_out = g_c[side][pp ^ 1];

    __shared__ float As[BM][KC + 1];
    __shared__ float Hs[BM][KC + 1];
    __shared__ float Wi[4][BJ][KC + 1];
    __shared__ float Wh[4][BJ][KC + 1];

    const int tid = threadIdx.x;
    const int ty = tid >> 5, tx = tid & 31;
    const int m0 = blockIdx.x * BM;
    const int jb = blockIdx.y * BJ;

    float acc[8][2][4];
#pragma unroll
    for (int r = 0; r < 8; r++)
#pragma unroll
        for (int u = 0; u < 2; u++)
#pragma unroll
            for (int g = 0; g < 4; g++) acc[r][u][g] = 0.0f;

    for (int kc = 0; kc < H; kc += KC) {
        // --- stage A/H tiles ---
#pragma unroll
        for (int i = tid; i < BM * KC; i += 256) {
            int m = i >> 4, k = i & 15;
            int mm = m0 + m;
            float xv = 0.0f, hv = 0.0f;
            if (mm < n) {
                long long row = xoff + (long long)mm * xstr;
                xv = xbase[row * H + kc + k];
                if (!first) hv = h_in[(long long)mm * H + kc + k];
            }
            As[m][k] = xv;
            Hs[m][k] = hv;
        }
        // --- stage weight tiles (4 gates x 64 j x 16 k) ---
#pragma unroll
        for (int i = tid; i < 4 * BJ * KC; i += 256) {
            int k = i & 15, jj = (i >> 4) & 63, g = i >> 10;
            long long row = (long long)(g * H + jb + jj);
            Wi[g][jj][k] = Wih[row * H + kc + k];
            Wh[g][jj][k] = first ? 0.0f : Whh[row * H + kc + k];
        }
        __syncthreads();

        if (first) {
#pragma unroll
            for (int k = 0; k < KC; k++) {
                float a[8];
#pragma unroll
                for (int r = 0; r < 8; r++) a[r] = As[ty * 8 + r][k];
                float wi0[4], wi1[4];
#pragma unroll
                for (int g = 0; g < 4; g++) { wi0[g] = Wi[g][tx][k]; wi1[g] = Wi[g][tx + 32][k]; }
#pragma unroll
                for (int r = 0; r < 8; r++)
#pragma unroll
                    for (int g = 0; g < 4; g++) {
                        acc[r][0][g] += a[r] * wi0[g];
                        acc[r][1][g] += a[r] * wi1[g];
                    }
            }
        } else {
#pragma unroll
            for (int k = 0; k < KC; k++) {
                float a[8], hh[8];
#pragma unroll
                for (int r = 0; r < 8; r++) { a[r] = As[ty * 8 + r][k]; hh[r] = Hs[ty * 8 + r][k]; }
                float wi0[4], wi1[4], wh0[4], wh1[4];
#pragma unroll
                for (int g = 0; g < 4; g++) {
                    wi0[g] = Wi[g][tx][k];      wi1[g] = Wi[g][tx + 32][k];
                    wh0[g] = Wh[g][tx][k];      wh1[g] = Wh[g][tx + 32][k];
                }
#pragma unroll
                for (int r = 0; r < 8; r++)
#pragma unroll
                    for (int g = 0; g < 4; g++) {
                        acc[r][0][g] += a[r] * wi0[g] + hh[r] * wh0[g];
                        acc[r][1][g] += a[r] * wi1[g] + hh[r] * wh1[g];
                    }
            }
        }
        __syncthreads();
    }

    // --- epilogue: gate nonlinearities + state update ---
#pragma unroll
    for (int r = 0; r < 8; r++) {
        int mm = m0 + ty * 8 + r;
        if (mm >= n) continue;
#pragma unroll
        for (int u = 0; u < 2; u++) {
            int j = jb + tx + u * 32;
            float gi = acc[r][u][0] + bih[j]         + bhh[j];
            float gf = acc[r][u][1] + bih[H + j]     + bhh[H + j];
            float gg = acc[r][u][2] + bih[2 * H + j] + bhh[2 * H + j];
            float go = acc[r][u][3] + bih[3 * H + j] + bhh[3 * H + j];
            float cprev = first ? 0.0f : c_in[(long long)mm * H + j];
            float c = sigm(gf) * cprev + sigm(gi) * tanhf(gg);
            float h = sigm(go) * tanhf(c);
            h_out[(long long)mm * H + j] = h;
            if (!last) c_out[(long long)mm * H + j] = c;
        }
    }
}

// enc = tanh([el, er] @ Wenc^T + benc), written to g_enc rows [off, off+n)
__global__ __launch_bounds__(256)
void enc_kernel(const float* __restrict__ Wenc, const float* __restrict__ benc,
                int n, long long off, float* __restrict__ outp)
{
    __shared__ float As[BM][KC + 1];
    __shared__ float Ws[BJ][KC + 1];

    const int tid = threadIdx.x;
    const int ty = tid >> 5, tx = tid & 31;
    const int m0 = blockIdx.x * BM;
    const int jb = blockIdx.y * BJ;

    float acc[8][2];
#pragma unroll
    for (int r = 0; r < 8; r++) { acc[r][0] = 0.0f; acc[r][1] = 0.0f; }

    for (int seg = 0; seg < 2; seg++) {
        const float* E = seg ? g_er : g_el;
        for (int kc = 0; kc < H; kc += KC) {
#pragma unroll
            for (int i = tid; i < BM * KC; i += 256) {
                int m = i >> 4, k = i & 15;
                int mm = m0 + m;
                As[m][k] = (mm < n) ? E[(long long)mm * H + kc + k] : 0.0f;
            }
#pragma unroll
            for (int i = tid; i < BJ * KC; i += 256) {
                int k = i & 15, jj = i >> 4;
                Ws[jj][k] = Wenc[(long long)(jb + jj) * (2 * H) + seg * H + kc + k];
            }
            __syncthreads();
#pragma unroll
            for (int k = 0; k < KC; k++) {
                float a[8];
#pragma unroll
                for (int r = 0; r < 8; r++) a[r] = As[ty * 8 + r][k];
                float w0 = Ws[tx][k], w1 = Ws[tx + 32][k];
#pragma unroll
                for (int r = 0; r < 8; r++) { acc[r][0] += a[r] * w0; acc[r][1] += a[r] * w1; }
            }
            __syncthreads();
        }
    }

#pragma unroll
    for (int r = 0; r < 8; r++) {
        int mm = m0 + ty * 8 + r;
        if (mm >= n) continue;
#pragma unroll
        for (int u = 0; u < 2; u++) {
            int j = jb + tx + u * 32;
            float v = tanhf(acc[r][u] + benc[j]);
            g_enc[(off + mm) * H + j] = v;
            if (outp != nullptr && mm == 0) outp[j] = v;
        }
    }
}

extern "C" void kernel_launch(void* const* d_in, const int* in_sizes, int n_in,
                              void* d_out, int out_size)
{
    const float* node_init = (const float*)d_in[0];
    const float* Wih_l = (const float*)d_in[1];
    const float* Whh_l = (const float*)d_in[2];
    const float* bih_l = (const float*)d_in[3];
    const float* bhh_l = (const float*)d_in[4];
    const float* Wih_r = (const float*)d_in[5];
    const float* Whh_r = (const float*)d_in[6];
    const float* bih_r = (const float*)d_in[7];
    const float* bhh_r = (const float*)d_in[8];
    const float* Wenc  = (const float*)d_in[9];
    const float* benc  = (const float*)d_in[10];
    float* out = (float*)d_out;

    static const int       SZ[7]  = {1, 8, 64, 512, 4096, 32768, 262144};
    static const long long OFF[7] = {0, 1, 9, 73, 585, 4681, 37449};

    // ---- leaf level d=6: T=1 LSTM (h0=c0=0), x = own rows of node_init ----
    {
        int n = SZ[6]; long long off = OFF[6];
        dim3 g((n + BM - 1) / BM, 4, 2);
        lstm_step_kernel<<<g, 256>>>(node_init,
            Wih_l, Whh_l, bih_l, bhh_l, Wih_r, Whh_r, bih_r, bhh_r,
            n, /*first=*/1, /*last=*/1, /*pp=*/0,
            /*xl*/ 0, off, 1, /*xr*/ 0, off, 1);
        dim3 ge((n + BM - 1) / BM, 4, 1);
        enc_kernel<<<ge, 256>>>(Wenc, benc, n, off, nullptr);
    }

    // ---- levels d=5..0: T=5 chains ----
    for (int d = 5; d >= 0; d--) {
        int n = SZ[d];
        long long off = OFF[d], coff = OFF[d + 1];
        dim3 g((n + BM - 1) / BM, 4, 2);
        dim3 ge((n + BM - 1) / BM, 4, 1);
        for (int t = 0; t < 5; t++) {
            int first = (t == 0), last = (t == 4), pp = (t & 1) ^ 1;
            // left chain:  t=0..3 -> child (3-t), t=4 -> own
            int xsl, xstr_l; long long xol;
            if (t < 4) { xsl = 1; xol = coff + (3 - t); xstr_l = 8; }
            else       { xsl = 0; xol = off;            xstr_l = 1; }
            // right chain: t=0 -> own, t=1..4 -> child (3+t)
            int xsr, xstr_r; long long xorr;
            if (t == 0) { xsr = 0; xorr = off;            xstr_r = 1; }
            else        { xsr = 1; xorr = coff + (3 + t); xstr_r = 8; }
            lstm_step_kernel<<<g, 256>>>(node_init,
                Wih_l, Whh_l, bih_l, bhh_l, Wih_r, Whh_r, bih_r, bhh_r,
                n, first, last, pp, xsl, xol, xstr_l, xsr, xorr, xstr_r);
        }
        enc_kernel<<<ge, 256>>>(Wenc, benc, n, off, (d == 0) ? out : nullptr);
    }
}

// round 11
// speedup vs baseline: 1.0021x; 1.0021x over previous
#include <cuda_runtime.h>
#include <math.h>

#define H 256

#define BM 64
#define BJ 64
#define KC 16

#define HMAX_ROWS 32768
#define LEAF_N    262144
#define N_TOTAL   299593

// Scratch (device globals -- no allocation allowed)
__device__ float g_enc[(size_t)N_TOTAL * H];          // encoder outputs per tree node
__device__ float g_el [(size_t)LEAF_N  * H];          // left-LSTM final hidden
__device__ float g_er [(size_t)LEAF_N  * H];          // right-LSTM final hidden
__device__ float g_h[2][2][(size_t)HMAX_ROWS * H];    // [side][ping] hidden state
__device__ float g_c[2][2][(size_t)HMAX_ROWS * H];    // [side][ping] cell state

__device__ __forceinline__ float sigm(float x) { return 1.0f / (1.0f + expf(-x)); }

// One LSTM step for both the left (z=0) and right (z=1) chains.
// gates[n,1024] = X[n,256] @ Wih^T (+ Hprev[n,256] @ Whh^T) + bih + bhh
// X rows come from node_init (xsrc=0) or g_enc (xsrc=1) at row = xoff + m*xstr.
__global__ __launch_bounds__(256)
void lstm_step_kernel(
    const float* __restrict__ node_init,
    const float* __restrict__ Wih_l, const float* __restrict__ Whh_l,
    const float* __restrict__ bih_l, const float* __restrict__ bhh_l,
    const float* __restrict__ Wih_r, const float* __restrict__ Whh_r,
    const float* __restrict__ bih_r, const float* __restrict__ bhh_r,
    int n, int first, int last, int pp,
    int xsrc_l, long long xoff_l, int xstr_l,
    int xsrc_r, long long xoff_r, int xstr_r)
{
    const int side = blockIdx.z;
    const float* Wih = side ? Wih_r : Wih_l;
    const float* Whh = side ? Whh_r : Whh_l;
    const float* bih = side ? bih_r : bih_l;
    const float* bhh = side ? bhh_r : bhh_l;
    const int       xsrc = side ? xsrc_r : xsrc_l;
    const long long xoff = side ? xoff_r : xoff_l;
    const int       xstr = side ? xstr_r : xstr_l;

    const float* xbase = xsrc ? g_enc : node_init;
    const float* h_in  = g_h[side][pp];
    const float* c_in  = g_c[side][pp];
    float* h_out = last ? (side ? g_er : g_el) : g_h[side][pp ^ 1];
    float* c_out = g_c[side][pp ^ 1];

    __shared__ float As[BM][KC + 1];
    __shared__ float Hs[BM][KC + 1];
    __shared__ float Wi[4][BJ][KC + 1];
    __shared__ float Wh[4][BJ][KC + 1];

    const int tid = threadIdx.x;
    const int ty = tid >> 5, tx = tid & 31;
    const int m0 = blockIdx.x * BM;
    const int jb = blockIdx.y * BJ;

    float acc[8][2][4];
#pragma unroll
    for (int r = 0; r < 8; r++)
#pragma unroll
        for (int u = 0; u < 2; u++)
#pragma unroll
            for (int g = 0; g < 4; g++) acc[r][u][g] = 0.0f;

    for (int kc = 0; kc < H; kc += KC) {
        // --- stage A/H tiles ---
#pragma unroll
        for (int i = tid; i < BM * KC; i += 256) {
            int m = i >> 4, k = i & 15;
            int mm = m0 + m;
            float xv = 0.0f, hv = 0.0f;
            if (mm < n) {
                long long row = xoff + (long long)mm * xstr;
                xv = xbase[row * H + kc + k];
                if (!first) hv = h_in[(long long)mm * H + kc + k];
            }
            As[m][k] = xv;
            Hs[m][k] = hv;
        }
        // --- stage weight tiles (4 gates x 64 j x 16 k) ---
#pragma unroll
        for (int i = tid; i < 4 * BJ * KC; i += 256) {
            int k = i & 15, jj = (i >> 4) & 63, g = i >> 10;
            long long row = (long long)(g * H + jb + jj);
            Wi[g][jj][k] = Wih[row * H + kc + k];
            Wh[g][jj][k] = first ? 0.0f : Whh[row * H + kc + k];
        }
        __syncthreads();

        if (first) {
#pragma unroll
            for (int k = 0; k < KC; k++) {
                float a[8];
#pragma unroll
                for (int r = 0; r < 8; r++) a[r] = As[ty * 8 + r][k];
                float wi0[4], wi1[4];
#pragma unroll
                for (int g = 0; g < 4; g++) { wi0[g] = Wi[g][tx][k]; wi1[g] = Wi[g][tx + 32][k]; }
#pragma unroll
                for (int r = 0; r < 8; r++)
#pragma unroll
                    for (int g = 0; g < 4; g++) {
                        acc[r][0][g] += a[r] * wi0[g];
                        acc[r][1][g] += a[r] * wi1[g];
                    }
            }
        } else {
#pragma unroll
            for (int k = 0; k < KC; k++) {
                float a[8], hh[8];
#pragma unroll
                for (int r = 0; r < 8; r++) { a[r] = As[ty * 8 + r][k]; hh[r] = Hs[ty * 8 + r][k]; }
                float wi0[4], wi1[4], wh0[4], wh1[4];
#pragma unroll
                for (int g = 0; g < 4; g++) {
                    wi0[g] = Wi[g][tx][k];      wi1[g] = Wi[g][tx + 32][k];
                    wh0[g] = Wh[g][tx][k];      wh1[g] = Wh[g][tx + 32][k];
                }
#pragma unroll
                for (int r = 0; r < 8; r++)
#pragma unroll
                    for (int g = 0; g < 4; g++) {
                        acc[r][0][g] += a[r] * wi0[g] + hh[r] * wh0[g];
                        acc[r][1][g] += a[r] * wi1[g] + hh[r] * wh1[g];
                    }
            }
        }
        __syncthreads();
    }

    // --- epilogue: gate nonlinearities + state update ---
#pragma unroll
    for (int r = 0; r < 8; r++) {
        int mm = m0 + ty * 8 + r;
        if (mm >= n) continue;
#pragma unroll
        for (int u = 0; u < 2; u++) {
            int j = jb + tx + u * 32;
            float gi = acc[r][u][0] + bih[j]         + bhh[j];
            float gf = acc[r][u][1] + bih[H + j]     + bhh[H + j];
            float gg = acc[r][u][2] + bih[2 * H + j] + bhh[2 * H + j];
            float go = acc[r][u][3] + bih[3 * H + j] + bhh[3 * H + j];
            float cprev = first ? 0.0f : c_in[(long long)mm * H + j];
            float c = sigm(gf) * cprev + sigm(gi) * tanhf(gg);
            float h = sigm(go) * tanhf(c);
            h_out[(long long)mm * H + j] = h;
            if (!last) c_out[(long long)mm * H + j] = c;
        }
    }
}

// enc = tanh([el, er] @ Wenc^T + benc), written to g_enc rows [off, off+n)
__global__ __launch_bounds__(256)
void enc_kernel(const float* __restrict__ Wenc, const float* __restrict__ benc,
                int n, long long off, float* __restrict__ outp)
{
    __shared__ float As[BM][KC + 1];
    __shared__ float Ws[BJ][KC + 1];

    const int tid = threadIdx.x;
    const int ty = tid >> 5, tx = tid & 31;
    const int m0 = blockIdx.x * BM;
    const int jb = blockIdx.y * BJ;

    float acc[8][2];
#pragma unroll
    for (int r = 0; r < 8; r++) { acc[r][0] = 0.0f; acc[r][1] = 0.0f; }

    for (int seg = 0; seg < 2; seg++) {
        const float* E = seg ? g_er : g_el;
        for (int kc = 0; kc < H; kc += KC) {
#pragma unroll
            for (int i = tid; i < BM * KC; i += 256) {
                int m = i >> 4, k = i & 15;
                int mm = m0 + m;
                As[m][k] = (mm < n) ? E[(long long)mm * H + kc + k] : 0.0f;
            }
#pragma unroll
            for (int i = tid; i < BJ * KC; i += 256) {
                int k = i & 15, jj = i >> 4;
                Ws[jj][k] = Wenc[(long long)(jb + jj) * (2 * H) + seg * H + kc + k];
            }
            __syncthreads();
#pragma unroll
            for (int k = 0; k < KC; k++) {
                float a[8];
#pragma unroll
                for (int r = 0; r < 8; r++) a[r] = As[ty * 8 + r][k];
                float w0 = Ws[tx][k], w1 = Ws[tx + 32][k];
#pragma unroll
                for (int r = 0; r < 8; r++) { acc[r][0] += a[r] * w0; acc[r][1] += a[r] * w1; }
            }
            __syncthreads();
        }
    }

#pragma unroll
    for (int r = 0; r < 8; r++) {
        int mm = m0 + ty * 8 + r;
        if (mm >= n) continue;
#pragma unroll
        for (int u = 0; u < 2; u++) {
            int j = jb + tx + u * 32;
            float v = tanhf(acc[r][u] + benc[j]);
            g_enc[(off + mm) * H + j] = v;
            if (outp != nullptr && mm == 0) outp[j] = v;
        }
    }
}

extern "C" void kernel_launch(void* const* d_in, const int* in_sizes, int n_in,
                              void* d_out, int out_size)
{
    const float* node_init = (const float*)d_in[0];
    const float* Wih_l = (const float*)d_in[1];
    const float* Whh_l = (const float*)d_in[2];
    const float* bih_l = (const float*)d_in[3];
    const float* bhh_l = (const float*)d_in[4];
    const float* Wih_r = (const float*)d_in[5];
    const float* Whh_r = (const float*)d_in[6];
    const float* bih_r = (const float*)d_in[7];
    const float* bhh_r = (const float*)d_in[8];
    const float* Wenc  = (const float*)d_in[9];
    const float* benc  = (const float*)d_in[10];
    float* out = (float*)d_out;

    static const int       SZ[7]  = {1, 8, 64, 512, 4096, 32768, 262144};
    static const long long OFF[7] = {0, 1, 9, 73, 585, 4681, 37449};

    // ---- leaf level d=6: T=1 LSTM (h0=c0=0), x = own rows of node_init ----
    {
        int n = SZ[6]; long long off = OFF[6];
        dim3 g((n + BM - 1) / BM, 4, 2);
        lstm_step_kernel<<<g, 256>>>(node_init,
            Wih_l, Whh_l, bih_l, bhh_l, Wih_r, Whh_r, bih_r, bhh_r,
            n, /*first=*/1, /*last=*/1, /*pp=*/0,
            /*xl*/ 0, off, 1, /*xr*/ 0, off, 1);
        dim3 ge((n + BM - 1) / BM, 4, 1);
        enc_kernel<<<ge, 256>>>(Wenc, benc, n, off, nullptr);
    }

    // ---- levels d=5..0: T=5 chains ----
    for (int d = 5; d >= 0; d--) {
        int n = SZ[d];
        long long off = OFF[d], coff = OFF[d + 1];
        dim3 g((n + BM - 1) / BM, 4, 2);
        dim3 ge((n + BM - 1) / BM, 4, 1);
        for (int t = 0; t < 5; t++) {
            int first = (t == 0), last = (t == 4), pp = (t & 1) ^ 1;
            // left chain:  t=0..3 -> child (3-t), t=4 -> own
            int xsl, xstr_l; long long xol;
            if (t < 4) { xsl = 1; xol = coff + (3 - t); xstr_l = 8; }
            else       { xsl = 0; xol = off;            xstr_l = 1; }
            // right chain: t=0 -> own, t=1..4 -> child (3+t)
            int xsr, xstr_r; long long xorr;
            if (t == 0) { xsr = 0; xorr = off;            xstr_r = 1; }
            else        { xsr = 1; xorr = coff + (3 + t); xstr_r = 8; }
            lstm_step_kernel<<<g, 256>>>(node_init,
                Wih_l, Whh_l, bih_l, bhh_l, Wih_r, Whh_r, bih_r, bhh_r,
                n, first, last, pp, xsl, xol, xstr_l, xsr, xorr, xstr_r);
        }
        enc_kernel<<<ge, 256>>>(Wenc, benc, n, off, (d == 0) ? out : nullptr);
    }
}

// round 12
// speedup vs baseline: 1.1905x; 1.1880x over previous
#include <cuda_runtime.h>
#include <math.h>

#define H 256

#define BM 64
#define BJ 64
#define KC 16

#define HMAX_ROWS 32768
#define LEAF_N    262144
#define N_TOTAL   299593

// Scratch (device globals -- no allocation allowed)
__device__ float g_enc[(size_t)N_TOTAL * H];          // encoder outputs per tree node
__device__ float g_el [(size_t)LEAF_N  * H];          // left-LSTM final hidden
__device__ float g_er [(size_t)LEAF_N  * H];          // right-LSTM final hidden
__device__ float g_h[2][2][(size_t)HMAX_ROWS * H];    // [side][ping] hidden state
__device__ float g_c[2][2][(size_t)HMAX_ROWS * H];    // [side][ping] cell state

__device__ __forceinline__ float sigm(float x) { return 1.0f / (1.0f + expf(-x)); }

// ---- packed fp32x2 helpers (sm_103a FFMA2 path, PTX-only) ----
__device__ __forceinline__ unsigned long long pack2(float lo, float hi) {
    unsigned long long r;
    asm("mov.b64 %0, {%1, %2};" : "=l"(r)
        : "r"(__float_as_uint(lo)), "r"(__float_as_uint(hi)));
    return r;
}
__device__ __forceinline__ void unpack2(unsigned long long v, float& lo, float& hi) {
    unsigned int a, b;
    asm("mov.b64 {%0, %1}, %2;" : "=r"(a), "=r"(b) : "l"(v));
    lo = __uint_as_float(a);
    hi = __uint_as_float(b);
}
#define FFMA2(acc, a, b) \
    asm("fma.rn.f32x2 %0, %1, %2, %0;" : "+l"(acc) : "l"(a), "l"(b))

// One LSTM step for both the left (z=0) and right (z=1) chains.
// gates[n,1024] = X[n,256] @ Wih^T (+ Hprev[n,256] @ Whh^T) + bih + bhh
// X rows come from node_init (xsrc=0) or g_enc (xsrc=1) at row = xoff + m*xstr.
__global__ __launch_bounds__(256)
void lstm_step_kernel(
    const float* __restrict__ node_init,
    const float* __restrict__ Wih_l, const float* __restrict__ Whh_l,
    const float* __restrict__ bih_l, const float* __restrict__ bhh_l,
    const float* __restrict__ Wih_r, const float* __restrict__ Whh_r,
    const float* __restrict__ bih_r, const float* __restrict__ bhh_r,
    int n, int first, int last, int pp,
    int xsrc_l, long long xoff_l, int xstr_l,
    int xsrc_r, long long xoff_r, int xstr_r)
{
    const int side = blockIdx.z;
    const float* Wih = side ? Wih_r : Wih_l;
    const float* Whh = side ? Whh_r : Whh_l;
    const float* bih = side ? bih_r : bih_l;
    const float* bhh = side ? bhh_r : bhh_l;
    const int       xsrc = side ? xsrc_r : xsrc_l;
    const long long xoff = side ? xoff_r : xoff_l;
    const int       xstr = side ? xstr_r : xstr_l;

    const float* xbase = xsrc ? g_enc : node_init;
    const float* h_in  = g_h[side][pp];
    const float* c_in  = g_c[side][pp];
    float* h_out = last ? (side ? g_er : g_el) : g_h[side][pp ^ 1];
    float* c_out = g_c[side][pp ^ 1];

    __shared__ float As[BM][KC + 1];
    __shared__ float Hs[BM][KC + 1];
    __shared__ float Wi[4][BJ][KC + 1];
    __shared__ float Wh[4][BJ][KC + 1];

    const int tid = threadIdx.x;
    const int ty = tid >> 5, tx = tid & 31;
    const int m0 = blockIdx.x * BM;
    const int jb = blockIdx.y * BJ;

    // packed accumulators: lane pair (j = jb+tx, j = jb+tx+32)
    unsigned long long acc[8][4];
#pragma unroll
    for (int r = 0; r < 8; r++)
#pragma unroll
        for (int g = 0; g < 4; g++) acc[r][g] = 0ull;

    for (int kc = 0; kc < H; kc += KC) {
        // --- stage A/H tiles ---
#pragma unroll
        for (int i = tid; i < BM * KC; i += 256) {
            int m = i >> 4, k = i & 15;
            int mm = m0 + m;
            float xv = 0.0f, hv = 0.0f;
            if (mm < n) {
                long long row = xoff + (long long)mm * xstr;
                xv = xbase[row * H + kc + k];
                if (!first) hv = h_in[(long long)mm * H + kc + k];
            }
            As[m][k] = xv;
            Hs[m][k] = hv;
        }
        // --- stage weight tiles (4 gates x 64 j x 16 k) ---
#pragma unroll
        for (int i = tid; i < 4 * BJ * KC; i += 256) {
            int k = i & 15, jj = (i >> 4) & 63, g = i >> 10;
            long long row = (long long)(g * H + jb + jj);
            Wi[g][jj][k] = Wih[row * H + kc + k];
            Wh[g][jj][k] = first ? 0.0f : Whh[row * H + kc + k];
        }
        __syncthreads();

        if (first) {
#pragma unroll
            for (int k = 0; k < KC; k++) {
                unsigned long long a2[8];
#pragma unroll
                for (int r = 0; r < 8; r++) {
                    float a = As[ty * 8 + r][k];
                    a2[r] = pack2(a, a);
                }
                unsigned long long wip[4];
#pragma unroll
                for (int g = 0; g < 4; g++)
                    wip[g] = pack2(Wi[g][tx][k], Wi[g][tx + 32][k]);
#pragma unroll
                for (int r = 0; r < 8; r++)
#pragma unroll
                    for (int g = 0; g < 4; g++)
                        FFMA2(acc[r][g], a2[r], wip[g]);
            }
        } else {
#pragma unroll
            for (int k = 0; k < KC; k++) {
                unsigned long long a2[8], h2[8];
#pragma unroll
                for (int r = 0; r < 8; r++) {
                    float a = As[ty * 8 + r][k];
                    float hh = Hs[ty * 8 + r][k];
                    a2[r] = pack2(a, a);
                    h2[r] = pack2(hh, hh);
                }
                unsigned long long wip[4], whp[4];
#pragma unroll
                for (int g = 0; g < 4; g++) {
                    wip[g] = pack2(Wi[g][tx][k], Wi[g][tx + 32][k]);
                    whp[g] = pack2(Wh[g][tx][k], Wh[g][tx + 32][k]);
                }
#pragma unroll
                for (int r = 0; r < 8; r++)
#pragma unroll
                    for (int g = 0; g < 4; g++) {
                        FFMA2(acc[r][g], a2[r], wip[g]);
                        FFMA2(acc[r][g], h2[r], whp[g]);
                    }
            }
        }
        __syncthreads();
    }

    // --- epilogue: gate nonlinearities + state update ---
#pragma unroll
    for (int r = 0; r < 8; r++) {
        int mm = m0 + ty * 8 + r;
        if (mm >= n) continue;
        float av[2][4];
#pragma unroll
        for (int g = 0; g < 4; g++) unpack2(acc[r][g], av[0][g], av[1][g]);
#pragma unroll
        for (int u = 0; u < 2; u++) {
            int j = jb + tx + u * 32;
            float gi = av[u][0] + bih[j]         + bhh[j];
            float gf = av[u][1] + bih[H + j]     + bhh[H + j];
            float gg = av[u][2] + bih[2 * H + j] + bhh[2 * H + j];
            float go = av[u][3] + bih[3 * H + j] + bhh[3 * H + j];
            float cprev = first ? 0.0f : c_in[(long long)mm * H + j];
            float c = sigm(gf) * cprev + sigm(gi) * tanhf(gg);
            float h = sigm(go) * tanhf(c);
            h_out[(long long)mm * H + j] = h;
            if (!last) c_out[(long long)mm * H + j] = c;
        }
    }
}

// enc = tanh([el, er] @ Wenc^T + benc), written to g_enc rows [off, off+n)
__global__ __launch_bounds__(256)
void enc_kernel(const float* __restrict__ Wenc, const float* __restrict__ benc,
                int n, long long off, float* __restrict__ outp)
{
    __shared__ float As[BM][KC + 1];
    __shared__ float Ws[BJ][KC + 1];

    const int tid = threadIdx.x;
    const int ty = tid >> 5, tx = tid & 31;
    const int m0 = blockIdx.x * BM;
    const int jb = blockIdx.y * BJ;

    unsigned long long acc[8];
#pragma unroll
    for (int r = 0; r < 8; r++) acc[r] = 0ull;

    for (int seg = 0; seg < 2; seg++) {
        const float* E = seg ? g_er : g_el;
        for (int kc = 0; kc < H; kc += KC) {
#pragma unroll
            for (int i = tid; i < BM * KC; i += 256) {
                int m = i >> 4, k = i & 15;
                int mm = m0 + m;
                As[m][k] = (mm < n) ? E[(long long)mm * H + kc + k] : 0.0f;
            }
#pragma unroll
            for (int i = tid; i < BJ * KC; i += 256) {
                int k = i & 15, jj = i >> 4;
                Ws[jj][k] = Wenc[(long long)(jb + jj) * (2 * H) + seg * H + kc + k];
            }
            __syncthreads();
#pragma unroll
            for (int k = 0; k < KC; k++) {
                unsigned long long w2 = pack2(Ws[tx][k], Ws[tx + 32][k]);
#pragma unroll
                for (int r = 0; r < 8; r++) {
                    float a = As[ty * 8 + r][k];
                    unsigned long long a2 = pack2(a, a);
                    FFMA2(acc[r], a2, w2);
                }
            }
            __syncthreads();
        }
    }

#pragma unroll
    for (int r = 0; r < 8; r++) {
        int mm = m0 + ty * 8 + r;
        if (mm >= n) continue;
        float a0, a1;
        unpack2(acc[r], a0, a1);
#pragma unroll
        for (int u = 0; u < 2; u++) {
            int j = jb + tx + u * 32;
            float v = tanhf((u ? a1 : a0) + benc[j]);
            g_enc[(off + mm) * H + j] = v;
            if (outp != nullptr && mm == 0) outp[j] = v;
        }
    }
}

extern "C" void kernel_launch(void* const* d_in, const int* in_sizes, int n_in,
                              void* d_out, int out_size)
{
    const float* node_init = (const float*)d_in[0];
    const float* Wih_l = (const float*)d_in[1];
    const float* Whh_l = (const float*)d_in[2];
    const float* bih_l = (const float*)d_in[3];
    const float* bhh_l = (const float*)d_in[4];
    const float* Wih_r = (const float*)d_in[5];
    const float* Whh_r = (const float*)d_in[6];
    const float* bih_r = (const float*)d_in[7];
    const float* bhh_r = (const float*)d_in[8];
    const float* Wenc  = (const float*)d_in[9];
    const float* benc  = (const float*)d_in[10];
    float* out = (float*)d_out;

    static const int       SZ[7]  = {1, 8, 64, 512, 4096, 32768, 262144};
    static const long long OFF[7] = {0, 1, 9, 73, 585, 4681, 37449};

    // ---- leaf level d=6: T=1 LSTM (h0=c0=0), x = own rows of node_init ----
    {
        int n = SZ[6]; long long off = OFF[6];
        dim3 g((n + BM - 1) / BM, 4, 2);
        lstm_step_kernel<<<g, 256>>>(node_init,
            Wih_l, Whh_l, bih_l, bhh_l, Wih_r, Whh_r, bih_r, bhh_r,
            n, /*first=*/1, /*last=*/1, /*pp=*/0,
            /*xl*/ 0, off, 1, /*xr*/ 0, off, 1);
        dim3 ge((n + BM - 1) / BM, 4, 1);
        enc_kernel<<<ge, 256>>>(Wenc, benc, n, off, nullptr);
    }

    // ---- levels d=5..0: T=5 chains ----
    for (int d = 5; d >= 0; d--) {
        int n = SZ[d];
        long long off = OFF[d], coff = OFF[d + 1];
        dim3 g((n + BM - 1) / BM, 4, 2);
        dim3 ge((n + BM - 1) / BM, 4, 1);
        for (int t = 0; t < 5; t++) {
            int first = (t == 0), last = (t == 4), pp = (t & 1) ^ 1;
            // left chain:  t=0..3 -> child (3-t), t=4 -> own
            int xsl, xstr_l; long long xol;
            if (t < 4) { xsl = 1; xol = coff + (3 - t); xstr_l = 8; }
            else       { xsl = 0; xol = off;            xstr_l = 1; }
            // right chain: t=0 -> own, t=1..4 -> child (3+t)
            int xsr, xstr_r; long long xorr;
            if (t == 0) { xsr = 0; xorr = off;            xstr_r = 1; }
            else        { xsr = 1; xorr = coff + (3 + t); xstr_r = 8; }
            lstm_step_kernel<<<g, 256>>>(node_init,
                Wih_l, Whh_l, bih_l, bhh_l, Wih_r, Whh_r, bih_r, bhh_r,
                n, first, last, pp, xsl, xol, xstr_l, xsr, xorr, xstr_r);
        }
        enc_kernel<<<ge, 256>>>(Wenc, benc, n, off, (d == 0) ? out : nullptr);
    }
}

// round 13
// speedup vs baseline: 1.1942x; 1.0031x over previous
#include <cuda_runtime.h>
#include <math.h>

#define H 256

#define BM 64
#define BJ 64
#define KC 16

#define HMAX_ROWS 32768
#define LEAF_N    262144
#define N_TOTAL   299593

// Scratch (device globals -- no allocation allowed)
__device__ float g_enc[(size_t)N_TOTAL * H];          // encoder outputs per tree node
__device__ float g_el [(size_t)LEAF_N  * H];          // left-LSTM final hidden
__device__ float g_er [(size_t)LEAF_N  * H];          // right-LSTM final hidden
__device__ float g_h[2][2][(size_t)HMAX_ROWS * H];    // [side][ping] hidden state
__device__ float g_c[2][2][(size_t)HMAX_ROWS * H];    // [side][ping] cell state

__device__ __forceinline__ float sigm(float x) { return 1.0f / (1.0f + expf(-x)); }

// ---- packed fp32x2 helpers (sm_103a FFMA2 path, PTX-only) ----
__device__ __forceinline__ unsigned long long pack2(float lo, float hi) {
    unsigned long long r;
    asm("mov.b64 %0, {%1, %2};" : "=l"(r)
        : "r"(__float_as_uint(lo)), "r"(__float_as_uint(hi)));
    return r;
}
__device__ __forceinline__ void unpack2(unsigned long long v, float& lo, float& hi) {
    unsigned int a, b;
    asm("mov.b64 {%0, %1}, %2;" : "=r"(a), "=r"(b) : "l"(v));
    lo = __uint_as_float(a);
    hi = __uint_as_float(b);
}
#define FFMA2(acc, a, b) \
    asm("fma.rn.f32x2 %0, %1, %2, %0;" : "+l"(acc) : "l"(a), "l"(b))

// One LSTM step for both the left (z=0) and right (z=1) chains.
// gates[n,1024] = X[n,256] @ Wih^T (+ Hprev[n,256] @ Whh^T) + bih + bhh
// X rows come from node_init (xsrc=0) or g_enc (xsrc=1) at row = xoff + m*xstr.
__global__ __launch_bounds__(256)
void lstm_step_kernel(
    const float* __restrict__ node_init,
    const float* __restrict__ Wih_l, const float* __restrict__ Whh_l,
    const float* __restrict__ bih_l, const float* __restrict__ bhh_l,
    const float* __restrict__ Wih_r, const float* __restrict__ Whh_r,
    const float* __restrict__ bih_r, const float* __restrict__ bhh_r,
    int n, int first, int last, int pp,
    int xsrc_l, long long xoff_l, int xstr_l,
    int xsrc_r, long long xoff_r, int xstr_r)
{
    const int side = blockIdx.z;
    const float* Wih = side ? Wih_r : Wih_l;
    const float* Whh = side ? Whh_r : Whh_l;
    const float* bih = side ? bih_r : bih_l;
    const float* bhh = side ? bhh_r : bhh_l;
    const int       xsrc = side ? xsrc_r : xsrc_l;
    const long long xoff = side ? xoff_r : xoff_l;
    const int       xstr = side ? xstr_r : xstr_l;

    const float* xbase = xsrc ? g_enc : node_init;
    const float* h_in  = g_h[side][pp];
    const float* c_in  = g_c[side][pp];
    float* h_out = last ? (side ? g_er : g_el) : g_h[side][pp ^ 1];
    float* c_out = g_c[side][pp ^ 1];

    __shared__ float As[BM][KC + 1];
    __shared__ float Hs[BM][KC + 1];
    __shared__ float Wi[4][BJ][KC + 1];
    __shared__ float Wh[4][BJ][KC + 1];

    const int tid = threadIdx.x;
    const int ty = tid >> 5, tx = tid & 31;
    const int m0 = blockIdx.x * BM;
    const int jb = blockIdx.y * BJ;

    // packed accumulators: lane pair (j = jb+tx, j = jb+tx+32)
    unsigned long long acc[8][4];
#pragma unroll
    for (int r = 0; r < 8; r++)
#pragma unroll
        for (int g = 0; g < 4; g++) acc[r][g] = 0ull;

    for (int kc = 0; kc < H; kc += KC) {
        // --- stage A/H tiles ---
#pragma unroll
        for (int i = tid; i < BM * KC; i += 256) {
            int m = i >> 4, k = i & 15;
            int mm = m0 + m;
            float xv = 0.0f, hv = 0.0f;
            if (mm < n) {
                long long row = xoff + (long long)mm * xstr;
                xv = xbase[row * H + kc + k];
                if (!first) hv = h_in[(long long)mm * H + kc + k];
            }
            As[m][k] = xv;
            Hs[m][k] = hv;
        }
        // --- stage weight tiles (4 gates x 64 j x 16 k) ---
#pragma unroll
        for (int i = tid; i < 4 * BJ * KC; i += 256) {
            int k = i & 15, jj = (i >> 4) & 63, g = i >> 10;
            long long row = (long long)(g * H + jb + jj);
            Wi[g][jj][k] = Wih[row * H + kc + k];
            Wh[g][jj][k] = first ? 0.0f : Whh[row * H + kc + k];
        }
        __syncthreads();

        if (first) {
#pragma unroll
            for (int k = 0; k < KC; k++) {
                unsigned long long a2[8];
#pragma unroll
                for (int r = 0; r < 8; r++) {
                    float a = As[ty * 8 + r][k];
                    a2[r] = pack2(a, a);
                }
                unsigned long long wip[4];
#pragma unroll
                for (int g = 0; g < 4; g++)
                    wip[g] = pack2(Wi[g][tx][k], Wi[g][tx + 32][k]);
#pragma unroll
                for (int r = 0; r < 8; r++)
#pragma unroll
                    for (int g = 0; g < 4; g++)
                        FFMA2(acc[r][g], a2[r], wip[g]);
            }
        } else {
#pragma unroll
            for (int k = 0; k < KC; k++) {
                unsigned long long a2[8], h2[8];
#pragma unroll
                for (int r = 0; r < 8; r++) {
                    float a = As[ty * 8 + r][k];
                    float hh = Hs[ty * 8 + r][k];
                    a2[r] = pack2(a, a);
                    h2[r] = pack2(hh, hh);
                }
                unsigned long long wip[4], whp[4];
#pragma unroll
                for (int g = 0; g < 4; g++) {
                    wip[g] = pack2(Wi[g][tx][k], Wi[g][tx + 32][k]);
                    whp[g] = pack2(Wh[g][tx][k], Wh[g][tx + 32][k]);
                }
#pragma unroll
                for (int r = 0; r < 8; r++)
#pragma unroll
                    for (int g = 0; g < 4; g++) {
                        FFMA2(acc[r][g], a2[r], wip[g]);
                        FFMA2(acc[r][g], h2[r], whp[g]);
                    }
            }
        }
        __syncthreads();
    }

    // --- epilogue: gate nonlinearities + state update ---
#pragma unroll
    for (int r = 0; r < 8; r++) {
        int mm = m0 + ty * 8 + r;
        if (mm >= n) continue;
        float av[2][4];
#pragma unroll
        for (int g = 0; g < 4; g++) unpack2(acc[r][g], av[0][g], av[1][g]);
#pragma unroll
        for (int u = 0; u < 2; u++) {
            int j = jb + tx + u * 32;
            float gi = av[u][0] + bih[j]         + bhh[j];
            float gf = av[u][1] + bih[H + j]     + bhh[H + j];
            float gg = av[u][2] + bih[2 * H + j] + bhh[2 * H + j];
            float go = av[u][3] + bih[3 * H + j] + bhh[3 * H + j];
            float cprev = first ? 0.0f : c_in[(long long)mm * H + j];
            float c = sigm(gf) * cprev + sigm(gi) * tanhf(gg);
            float h = sigm(go) * tanhf(c);
            h_out[(long long)mm * H + j] = h;
            if (!last) c_out[(long long)mm * H + j] = c;
        }
    }
}

// enc = tanh([el, er] @ Wenc^T + benc), written to g_enc rows [off, off+n)
__global__ __launch_bounds__(256)
void enc_kernel(const float* __restrict__ Wenc, const float* __restrict__ benc,
                int n, long long off, float* __restrict__ outp)
{
    __shared__ float As[BM][KC + 1];
    __shared__ float Ws[BJ][KC + 1];

    const int tid = threadIdx.x;
    const int ty = tid >> 5, tx = tid & 31;
    const int m0 = blockIdx.x * BM;
    const int jb = blockIdx.y * BJ;

    unsigned long long acc[8];
#pragma unroll
    for (int r = 0; r < 8; r++) acc[r] = 0ull;

    for (int seg = 0; seg < 2; seg++) {
        const float* E = seg ? g_er : g_el;
        for (int kc = 0; kc < H; kc += KC) {
#pragma unroll
            for (int i = tid; i < BM * KC; i += 256) {
                int m = i >> 4, k = i & 15;
                int mm = m0 + m;
                As[m][k] = (mm < n) ? E[(long long)mm * H + kc + k] : 0.0f;
            }
#pragma unroll
            for (int i = tid; i < BJ * KC; i += 256) {
                int k = i & 15, jj = i >> 4;
                Ws[jj][k] = Wenc[(long long)(jb + jj) * (2 * H) + seg * H + kc + k];
            }
            __syncthreads();
#pragma unroll
            for (int k = 0; k < KC; k++) {
                unsigned long long w2 = pack2(Ws[tx][k], Ws[tx + 32][k]);
#pragma unroll
                for (int r = 0; r < 8; r++) {
                    float a = As[ty * 8 + r][k];
                    unsigned long long a2 = pack2(a, a);
                    FFMA2(acc[r], a2, w2);
                }
            }
            __syncthreads();
        }
    }

#pragma unroll
    for (int r = 0; r < 8; r++) {
        int mm = m0 + ty * 8 + r;
        if (mm >= n) continue;
        float a0, a1;
        unpack2(acc[r], a0, a1);
#pragma unroll
        for (int u = 0; u < 2; u++) {
            int j = jb + tx + u * 32;
            float v = tanhf((u ? a1 : a0) + benc[j]);
            g_enc[(off + mm) * H + j] = v;
            if (outp != nullptr && mm == 0) outp[j] = v;
        }
    }
}

extern "C" void kernel_launch(void* const* d_in, const int* in_sizes, int n_in,
                              void* d_out, int out_size)
{
    const float* node_init = (const float*)d_in[0];
    const float* Wih_l = (const float*)d_in[1];
    const float* Whh_l = (const float*)d_in[2];
    const float* bih_l = (const float*)d_in[3];
    const float* bhh_l = (const float*)d_in[4];
    const float* Wih_r = (const float*)d_in[5];
    const float* Whh_r = (const float*)d_in[6];
    const float* bih_r = (const float*)d_in[7];
    const float* bhh_r = (const float*)d_in[8];
    const float* Wenc  = (const float*)d_in[9];
    const float* benc  = (const float*)d_in[10];
    float* out = (float*)d_out;

    static const int       SZ[7]  = {1, 8, 64, 512, 4096, 32768, 262144};
    static const long long OFF[7] = {0, 1, 9, 73, 585, 4681, 37449};

    // ---- leaf level d=6: T=1 LSTM (h0=c0=0), x = own rows of node_init ----
    {
        int n = SZ[6]; long long off = OFF[6];
        dim3 g((n + BM - 1) / BM, 4, 2);
        lstm_step_kernel<<<g, 256>>>(node_init,
            Wih_l, Whh_l, bih_l, bhh_l, Wih_r, Whh_r, bih_r, bhh_r,
            n, /*first=*/1, /*last=*/1, /*pp=*/0,
            /*xl*/ 0, off, 1, /*xr*/ 0, off, 1);
        dim3 ge((n + BM - 1) / BM, 4, 1);
        enc_kernel<<<ge, 256>>>(Wenc, benc, n, off, nullptr);
    }

    // ---- levels d=5..0: T=5 chains ----
    for (int d = 5; d >= 0; d--) {
        int n = SZ[d];
        long long off = OFF[d], coff = OFF[d + 1];
        dim3 g((n + BM - 1) / BM, 4, 2);
        dim3 ge((n + BM - 1) / BM, 4, 1);
        for (int t = 0; t < 5; t++) {
            int first = (t == 0), last = (t == 4), pp = (t & 1) ^ 1;
            // left chain:  t=0..3 -> child (3-t), t=4 -> own
            int xsl, xstr_l; long long xol;
            if (t < 4) { xsl = 1; xol = coff + (3 - t); xstr_l = 8; }
            else       { xsl = 0; xol = off;            xstr_l = 1; }
            // right chain: t=0 -> own, t=1..4 -> child (3+t)
            int xsr, xstr_r; long long xorr;
            if (t == 0) { xsr = 0; xorr = off;            xstr_r = 1; }
            else        { xsr = 1; xorr = coff + (3 + t); xstr_r = 8; }
            lstm_step_kernel<<<g, 256>>>(node_init,
                Wih_l, Whh_l, bih_l, bhh_l, Wih_r, Whh_r, bih_r, bhh_r,
                n, first, last, pp, xsl, xol, xstr_l, xsr, xorr, xstr_r);
        }
        enc_kernel<<<ge, 256>>>(Wenc, benc, n, off, (d == 0) ? out : nullptr);
    }
}